// round 2
// baseline (speedup 1.0000x reference)
#include <cuda_runtime.h>
#include <math.h>

#define Bdim   2
#define Ldim   2048
#define DIMV   1024
#define NH     8
#define INNER  128
#define MROWS  (Bdim*Ldim)   /* 4096 */
#define EPSV   1e-5f

// ---------------- scratch (static __device__, no allocs) ----------------
__device__ float g_yact[(size_t)MROWS*DIMV];        // x @ W_y_act.T + b  (16 MB)
__device__ float g_spart[MROWS/64][DIMV];           // per-rowtile partial colsums of z
__device__ float g_zrows[Bdim][NH][DIMV];           // z rows l=0..7 (full width)
__device__ float g_lda [Bdim][NH][Ldim];            // ln_da
__device__ float g_Acum[Bdim][NH][Ldim];            // exp(cumsum ln_da)
__device__ float g_P[Bdim][NH][INNER];
__device__ float g_Q[Bdim][NH][INNER];
__device__ float g_vc[Bdim][NH], g_vt[Bdim][NH], g_cov[Bdim][NH];
__device__ float g_PW[Bdim][NH][DIMV];
__device__ float g_QW[Bdim][NH][DIMV];
__device__ float g_GW[DIMV];

// ---------------- K1a: dt projection (warp per row) ----------------
__global__ void k1_dt(const float* __restrict__ x, const float* __restrict__ Wdt,
                      const float* __restrict__ bdt, const float* __restrict__ lna)
{
    int gw   = (blockIdx.x * blockDim.x + threadIdx.x) >> 5;   // row id 0..4095
    int lane = threadIdx.x & 31;
    if (gw >= MROWS) return;
    const float* xr = x + (size_t)gw * DIMV;
    float acc[NH];
#pragma unroll
    for (int h = 0; h < NH; h++) acc[h] = 0.f;
    for (int k = lane; k < DIMV; k += 32) {
        float xv = xr[k];
#pragma unroll
        for (int h = 0; h < NH; h++) acc[h] += xv * Wdt[h*DIMV + k];
    }
#pragma unroll
    for (int h = 0; h < NH; h++)
        for (int off = 16; off; off >>= 1)
            acc[h] += __shfl_xor_sync(0xffffffffu, acc[h], off);
    if (lane == 0) {
        int b = gw >> 11, l = gw & (Ldim-1);
#pragma unroll
        for (int h = 0; h < NH; h++) {
            float v  = acc[h] + bdt[h];
            float sp = fmaxf(v, 0.f) + log1pf(expf(-fabsf(v)));   // stable softplus
            g_lda[b][h][l] = -expf(lna[h]) * sp;
        }
    }
}

// ---------------- K1b: inclusive scan + exp, per (b,h) ----------------
__global__ void k1b_scan()
{
    int b = blockIdx.x >> 3, h = blockIdx.x & 7;
    int t = threadIdx.x;                  // 256 threads, 8 elems each
    const float* src = g_lda[b][h];
    int base = t * 8;
    float v[8]; float s = 0.f;
#pragma unroll
    for (int u = 0; u < 8; u++) { v[u] = src[base+u]; s += v[u]; }
    __shared__ float sm[256];
    sm[t] = s; __syncthreads();
    for (int d = 1; d < 256; d <<= 1) {
        float add = (t >= d) ? sm[t-d] : 0.f;
        __syncthreads();
        sm[t] += add;
        __syncthreads();
    }
    float run = sm[t] - s;                // exclusive prefix
#pragma unroll
    for (int u = 0; u < 8; u++) { run += v[u]; g_Acum[b][h][base+u] = expf(run); }
}

// ---------------- K2: fused triple GEMM (x @ {Wz,Wza,Wya}.T) ----------------
// BM=BN=64, BK=16, 256 threads, 4x4x3 register tile. Epilogue:
//   - store y_act (+bias)
//   - z = lin*silu(act); masked colsum (l > head) -> deterministic partials
//   - stash z rows l<8
__global__ void __launch_bounds__(256)
k2_gemm(const float* __restrict__ x,
        const float* __restrict__ Wz,  const float* __restrict__ bz,
        const float* __restrict__ Wza, const float* __restrict__ bza,
        const float* __restrict__ Wya, const float* __restrict__ bya)
{
    __shared__ float As[16][64];
    __shared__ float Bs[3][16][64];
    __shared__ float red[16][64];

    int tid = threadIdx.x;
    int tx  = tid & 15, ty = tid >> 4;
    int j0  = blockIdx.x * 64;
    int r0  = blockIdx.y * 64;
    int lrow = tid >> 2;
    int lk   = (tid & 3) << 2;

    float acc[3][4][4];
#pragma unroll
    for (int m = 0; m < 3; m++)
#pragma unroll
        for (int i = 0; i < 4; i++)
#pragma unroll
            for (int c = 0; c < 4; c++) acc[m][i][c] = 0.f;

    const float* Ap = x   + (size_t)(r0+lrow)*DIMV + lk;
    const float* B0 = Wz  + (size_t)(j0+lrow)*DIMV + lk;
    const float* B1 = Wza + (size_t)(j0+lrow)*DIMV + lk;
    const float* B2 = Wya + (size_t)(j0+lrow)*DIMV + lk;

    for (int k0 = 0; k0 < DIMV; k0 += 16) {
        float4 a4  = *(const float4*)(Ap + k0);
        float4 b40 = *(const float4*)(B0 + k0);
        float4 b41 = *(const float4*)(B1 + k0);
        float4 b42 = *(const float4*)(B2 + k0);
        As[lk+0][lrow]=a4.x;  As[lk+1][lrow]=a4.y;  As[lk+2][lrow]=a4.z;  As[lk+3][lrow]=a4.w;
        Bs[0][lk+0][lrow]=b40.x; Bs[0][lk+1][lrow]=b40.y; Bs[0][lk+2][lrow]=b40.z; Bs[0][lk+3][lrow]=b40.w;
        Bs[1][lk+0][lrow]=b41.x; Bs[1][lk+1][lrow]=b41.y; Bs[1][lk+2][lrow]=b41.z; Bs[1][lk+3][lrow]=b41.w;
        Bs[2][lk+0][lrow]=b42.x; Bs[2][lk+1][lrow]=b42.y; Bs[2][lk+2][lrow]=b42.z; Bs[2][lk+3][lrow]=b42.w;
        __syncthreads();
#pragma unroll
        for (int k = 0; k < 16; k++) {
            float4 av  = *(const float4*)&As[k][ty<<2];
            float4 bv0 = *(const float4*)&Bs[0][k][tx<<2];
            float4 bv1 = *(const float4*)&Bs[1][k][tx<<2];
            float4 bv2 = *(const float4*)&Bs[2][k][tx<<2];
            float ar[4]  = {av.x, av.y, av.z, av.w};
            float br0[4] = {bv0.x,bv0.y,bv0.z,bv0.w};
            float br1[4] = {bv1.x,bv1.y,bv1.z,bv1.w};
            float br2[4] = {bv2.x,bv2.y,bv2.z,bv2.w};
#pragma unroll
            for (int i = 0; i < 4; i++) {
#pragma unroll
                for (int c = 0; c < 4; c++) {
                    acc[0][i][c] += ar[i]*br0[c];
                    acc[1][i][c] += ar[i]*br1[c];
                    acc[2][i][c] += ar[i]*br2[c];
                }
            }
        }
        __syncthreads();
    }

    // -------- epilogue --------
    int bIdx = r0 >> 11;
    int hblk = j0 >> 7;                           // head of this 64-col tile (64 | 128)
    bool firstTile = ((r0 & (Ldim-1)) == 0);
    int jb = j0 + (tx << 2);
    float bzv[4], bzav[4], byav[4];
#pragma unroll
    for (int c = 0; c < 4; c++) { bzv[c]=bz[jb+c]; bzav[c]=bza[jb+c]; byav[c]=bya[jb+c]; }

    float colsum[4] = {0.f,0.f,0.f,0.f};
#pragma unroll
    for (int i = 0; i < 4; i++) {
        int r = r0 + (ty<<2) + i;
        int l = r & (Ldim-1);
        float4 yv;
        yv.x = acc[2][i][0]+byav[0]; yv.y = acc[2][i][1]+byav[1];
        yv.z = acc[2][i][2]+byav[2]; yv.w = acc[2][i][3]+byav[3];
        *(float4*)(g_yact + (size_t)r*DIMV + jb) = yv;
#pragma unroll
        for (int c = 0; c < 4; c++) {
            float lin = acc[0][i][c] + bzv[c];
            float a   = acc[1][i][c] + bzav[c];
            float zv  = lin * (a / (1.f + expf(-a)));   // lin * silu(act)
            if (l > hblk) colsum[c] += zv;
            if (firstTile && l < NH) g_zrows[bIdx][l][jb+c] = zv;
        }
    }
#pragma unroll
    for (int c = 0; c < 4; c++) red[ty][(tx<<2)+c] = colsum[c];
    __syncthreads();
    if (tid < 64) {
        float s = 0.f;
#pragma unroll
        for (int t2 = 0; t2 < 16; t2++) s += red[t2][tid];
        g_spart[blockIdx.y][j0 + tid] = s;
    }
}

// ---------------- K3: per-(b,h) stats + P/Q + hidden_next ----------------
__device__ __forceinline__ float blockSum128(float v, float* sm)
{
    for (int off = 16; off; off >>= 1) v += __shfl_xor_sync(0xffffffffu, v, off);
    int w = threadIdx.x >> 5;
    if ((threadIdx.x & 31) == 0) sm[w] = v;
    __syncthreads();
    float r = sm[0] + sm[1] + sm[2] + sm[3];
    __syncthreads();
    return r;
}

__global__ void k3_stats(const float* __restrict__ hidden, const float* __restrict__ gnw,
                         float* __restrict__ out, int writeHidden)
{
    int b = blockIdx.x >> 3, h = blockIdx.x & 7;
    int i = threadIdx.x;                      // 128 threads
    int col = h*INNER + i;
    float S = 0.f;
#pragma unroll 8
    for (int t = 0; t < MROWS/64/Bdim; t++)   // 32 row tiles per batch
        S += g_spart[b*(MROWS/64/Bdim) + t][col];
    float c  = g_zrows[b][h][col];
    float tv = S + hidden[(b*NH+h)*INNER + i];

    __shared__ float sm[4];
    float mc = blockSum128(c,  sm) * (1.f/INNER);
    float mt = blockSum128(tv, sm) * (1.f/INNER);
    float dc = c - mc, dq = tv - mt;
    float vc = blockSum128(dc*dc, sm) * (1.f/INNER);
    float vt = blockSum128(dq*dq, sm) * (1.f/INNER);
    float cv = blockSum128(dc*dq, sm) * (1.f/INNER);
    if (i == 0) { g_vc[b][h]=vc; g_vt[b][h]=vt; g_cov[b][h]=cv; }
    float w = gnw[h];
    g_P[b][h][i] = dc * w;
    g_Q[b][h][i] = dq * w;
    if (writeHidden)
        out[(size_t)MROWS*DIMV + (b*NH+h)*INNER + i] = c + g_Acum[b][h][Ldim-1]*tv;
}

// ---------------- K4: rank-16 projections through W_y ----------------
__global__ void k4_proj(const float* __restrict__ Wy, const float* __restrict__ by,
                        const float* __restrict__ gnb)
{
    __shared__ float Ps[Bdim*NH*INNER];
    __shared__ float Qs[Bdim*NH*INNER];
    for (int idx = threadIdx.x; idx < Bdim*NH*INNER; idx += blockDim.x) {
        Ps[idx] = ((const float*)g_P)[idx];
        Qs[idx] = ((const float*)g_Q)[idx];
    }
    __syncthreads();
    int j    = (blockIdx.x * blockDim.x + threadIdx.x) >> 5;   // one warp per output col
    int lane = threadIdx.x & 31;
    if (j >= DIMV) return;
    const float* wrow = Wy + (size_t)j*DIMV;
    float gb = 0.f;
#pragma unroll
    for (int h = 0; h < NH; h++) {
        float aP0=0.f, aQ0=0.f, aP1=0.f, aQ1=0.f, aW=0.f;
#pragma unroll
        for (int kk = 0; kk < 4; kk++) {
            int ii = kk*32 + lane;
            float w = wrow[h*INNER + ii];
            aW  += w;
            aP0 += w * Ps[(0*NH+h)*INNER + ii];
            aQ0 += w * Qs[(0*NH+h)*INNER + ii];
            aP1 += w * Ps[(1*NH+h)*INNER + ii];
            aQ1 += w * Qs[(1*NH+h)*INNER + ii];
        }
        for (int off = 16; off; off >>= 1) {
            aP0 += __shfl_xor_sync(0xffffffffu, aP0, off);
            aQ0 += __shfl_xor_sync(0xffffffffu, aQ0, off);
            aP1 += __shfl_xor_sync(0xffffffffu, aP1, off);
            aQ1 += __shfl_xor_sync(0xffffffffu, aQ1, off);
            aW  += __shfl_xor_sync(0xffffffffu, aW,  off);
        }
        if (lane == 0) {
            g_PW[0][h][j] = aP0;  g_QW[0][h][j] = aQ0;
            g_PW[1][h][j] = aP1;  g_QW[1][h][j] = aQ1;
            gb += gnb[h] * aW;
        }
    }
    if (lane == 0) g_GW[j] = by[j] + gb;
}

// ---------------- K5: final y = (rank-16 combine) * silu(y_act) ----------------
__global__ void k5_final(float* __restrict__ out)
{
    int r = blockIdx.x;
    int b = r >> 11, l = r & (Ldim-1);
    __shared__ float cP[NH], cQ[NH];
    if (threadIdx.x < NH) {
        int h = threadIdx.x;
        float A   = g_Acum[b][h][l];
        float var = g_vc[b][h] + 2.f*A*g_cov[b][h] + A*A*g_vt[b][h];
        float inv = rsqrtf(var + EPSV);
        cP[h] = inv;
        cQ[h] = A * inv;
    }
    __syncthreads();
    for (int j = threadIdx.x; j < DIMV; j += blockDim.x) {
        float y0 = g_GW[j];
#pragma unroll
        for (int h = 0; h < NH; h++)
            y0 += cP[h]*g_PW[b][h][j] + cQ[h]*g_QW[b][h][j];
        float ya = g_yact[(size_t)r*DIMV + j];
        out[(size_t)r*DIMV + j] = y0 * (ya / (1.f + expf(-ya)));
    }
}

// ---------------- launch ----------------
extern "C" void kernel_launch(void* const* d_in, const int* in_sizes, int n_in,
                              void* d_out, int out_size)
{
    const float* x    = (const float*)d_in[0];
    const float* hid  = (const float*)d_in[1];
    const float* W_z  = (const float*)d_in[2];
    const float* b_z  = (const float*)d_in[3];
    const float* W_za = (const float*)d_in[4];
    const float* b_za = (const float*)d_in[5];
    const float* W_y  = (const float*)d_in[6];
    const float* b_y  = (const float*)d_in[7];
    const float* W_ya = (const float*)d_in[8];
    const float* b_ya = (const float*)d_in[9];
    const float* W_dt = (const float*)d_in[10];
    const float* b_dt = (const float*)d_in[11];
    const float* ln_a = (const float*)d_in[12];
    const float* gn_w = (const float*)d_in[13];
    const float* gn_b = (const float*)d_in[14];
    float* out = (float*)d_out;
    int writeHidden = (out_size >= MROWS*DIMV + Bdim*NH*INNER) ? 1 : 0;

    k1_dt  <<<MROWS/8, 256>>>(x, W_dt, b_dt, ln_a);
    k1b_scan<<<Bdim*NH, 256>>>();
    dim3 g2(DIMV/64, MROWS/64);
    k2_gemm<<<g2, 256>>>(x, W_z, b_z, W_za, b_za, W_ya, b_ya);
    k3_stats<<<Bdim*NH, INNER>>>(hid, gn_w, out, writeHidden);
    k4_proj<<<DIMV/8, 256>>>(W_y, b_y, gn_b);
    k5_final<<<MROWS, 256>>>(out);
}

// round 8
// speedup vs baseline: 2.4345x; 2.4345x over previous
#include <cuda_runtime.h>
#include <cuda_bf16.h>
#include <cstdint>
#include <math.h>

#define Bdim   2
#define Ldim   2048
#define DIMV   1024
#define NH     8
#define INNER  128
#define MROWS  (Bdim*Ldim)   /* 4096 */
#define NCAT   (3*DIMV)      /* 3072 */
#define EPSV   1e-5f

// ---------------- scratch (static __device__, no allocs) ----------------
__device__ __nv_bfloat16 g_xh[(size_t)MROWS*DIMV];
__device__ __nv_bfloat16 g_xl[(size_t)MROWS*DIMV];
__device__ __nv_bfloat16 g_wh[(size_t)NCAT*DIMV];
__device__ __nv_bfloat16 g_wl[(size_t)NCAT*DIMV];
__device__ float g_cat[(size_t)MROWS*NCAT];         // raw [lin | act | yact] (48MB)
__device__ float g_spart[MROWS/64][DIMV];
__device__ float g_zrows[Bdim][NH][DIMV];
__device__ float g_lda [Bdim][NH][Ldim];
__device__ float g_Acum[Bdim][NH][Ldim];
__device__ float g_P[Bdim][NH][INNER];
__device__ float g_Q[Bdim][NH][INNER];
__device__ float g_vc[Bdim][NH], g_vt[Bdim][NH], g_cov[Bdim][NH];
__device__ float g_PW[Bdim][NH][DIMV];
__device__ float g_QW[Bdim][NH][DIMV];
__device__ float g_GW[DIMV];

// ================= helpers =================
__device__ __forceinline__ uint32_t smem_u32(const void* p) {
    uint32_t a;
    asm("{ .reg .u64 t; cvta.to.shared.u64 t, %1; cvt.u32.u64 %0, t; }" : "=r"(a) : "l"(p));
    return a;
}
// 64-byte-row swizzle: toggles 16B-chunk index with (row>>1)&3
#define SWZ64(o) ((o) ^ (((o) >> 3) & 0x30))

__device__ __forceinline__ void cp16(uint32_t saddr, const void* g) {
    asm volatile("cp.async.cg.shared.global [%0], [%1], 16;" :: "r"(saddr), "l"(g));
}
#define CP_COMMIT()  asm volatile("cp.async.commit_group;" ::: "memory")
#define CP_WAIT0()   asm volatile("cp.async.wait_group 0;" ::: "memory")

__device__ __forceinline__ void ldmx4(uint32_t* r, uint32_t addr) {
    asm volatile("ldmatrix.sync.aligned.m8n8.x4.shared.b16 {%0,%1,%2,%3}, [%4];"
        : "=r"(r[0]), "=r"(r[1]), "=r"(r[2]), "=r"(r[3]) : "r"(addr));
}
__device__ __forceinline__ void mma16816(float* c, const uint32_t* a, const uint32_t* b) {
    asm volatile(
        "mma.sync.aligned.m16n8k16.row.col.f32.bf16.bf16.f32 "
        "{%0,%1,%2,%3},{%4,%5,%6,%7},{%8,%9},{%0,%1,%2,%3};"
        : "+f"(c[0]), "+f"(c[1]), "+f"(c[2]), "+f"(c[3])
        : "r"(a[0]), "r"(a[1]), "r"(a[2]), "r"(a[3]), "r"(b[0]), "r"(b[1]));
}

// ================= K0: fp32 -> bf16 hi/lo split =================
__global__ void kconv(const float* __restrict__ src, __nv_bfloat16* __restrict__ hi,
                      __nv_bfloat16* __restrict__ lo, int n4)
{
    int i = blockIdx.x * blockDim.x + threadIdx.x;
    if (i >= n4) return;
    float4 v = ((const float4*)src)[i];
    __nv_bfloat16 h0 = __float2bfloat16(v.x), h1 = __float2bfloat16(v.y);
    __nv_bfloat16 h2 = __float2bfloat16(v.z), h3 = __float2bfloat16(v.w);
    __nv_bfloat16 l0 = __float2bfloat16(v.x - __bfloat162float(h0));
    __nv_bfloat16 l1 = __float2bfloat16(v.y - __bfloat162float(h1));
    __nv_bfloat16 l2 = __float2bfloat16(v.z - __bfloat162float(h2));
    __nv_bfloat16 l3 = __float2bfloat16(v.w - __bfloat162float(h3));
    uint2 ph, pl;
    ph.x = ((uint32_t)__bfloat16_as_ushort(h1) << 16) | __bfloat16_as_ushort(h0);
    ph.y = ((uint32_t)__bfloat16_as_ushort(h3) << 16) | __bfloat16_as_ushort(h2);
    pl.x = ((uint32_t)__bfloat16_as_ushort(l1) << 16) | __bfloat16_as_ushort(l0);
    pl.y = ((uint32_t)__bfloat16_as_ushort(l3) << 16) | __bfloat16_as_ushort(l2);
    ((uint2*)hi)[i] = ph;
    ((uint2*)lo)[i] = pl;
}

// ================= GEMM: C[4096x3072] = X @ Wcat^T, mma.sync bf16 hi/lo =================
// BM=128, BN=128, BK=32. 256 threads = 8 warps (4 m x 2 n), warp tile 32x64.
#define OFF_AH 0
#define OFF_AL 8192
#define OFF_BH 16384
#define OFF_BL 24576
#define STG    32768
#define GEMM_SMEM (2*STG)

__global__ void __launch_bounds__(256)
kgemm_mma()
{
    extern __shared__ char smem[];
    const uint32_t sb = smem_u32(smem);
    const int tid = threadIdx.x;
    const int wid = tid >> 5, lane = tid & 31;
    const int wm = wid >> 1, wn = wid & 1;          // warp coords (4 x 2)
    const int n0 = blockIdx.x * 128;
    const int r0 = blockIdx.y * 128;

    float acc[2][8][4];
#pragma unroll
    for (int m = 0; m < 2; m++)
#pragma unroll
        for (int n = 0; n < 8; n++)
#pragma unroll
            for (int c = 0; c < 4; c++) acc[m][n][c] = 0.f;

    // ---- stage loader: 2048 chunks of 16B ----
    auto load_stage = [&](int stage, int kt) {
        uint32_t base = sb + stage * STG;
        int k0 = kt * 32;
#pragma unroll
        for (int u = 0; u < 8; u++) {
            int i = tid + u * 256;                  // 0..2047
            int mat = i >> 9;                       // 0:AH 1:AL 2:BH 3:BL
            int idx = i & 511;
            int row = idx >> 2, c = idx & 3;
            uint32_t so = SWZ64((uint32_t)(row*64 + c*16));
            uint32_t dst = base + mat*8192 + so;
            const __nv_bfloat16* src;
            if (mat == 0)      src = g_xh + (size_t)(r0+row)*DIMV + k0 + c*8;
            else if (mat == 1) src = g_xl + (size_t)(r0+row)*DIMV + k0 + c*8;
            else if (mat == 2) src = g_wh + (size_t)(n0+row)*DIMV + k0 + c*8;
            else               src = g_wl + (size_t)(n0+row)*DIMV + k0 + c*8;
            cp16(dst, src);
        }
    };

    load_stage(0, 0);
    CP_COMMIT();

    for (int it = 0; it < 32; it++) {
        CP_WAIT0();
        __syncthreads();
        if (it + 1 < 32) { load_stage((it+1) & 1, it+1); CP_COMMIT(); }

        uint32_t stg = sb + (it & 1) * STG;
#pragma unroll
        for (int kh = 0; kh < 2; kh++) {
            // --- A fragments (hi, lo): 2 m16 tiles each ---
            uint32_t ah[2][4], al[2][4];
#pragma unroll
            for (int m = 0; m < 2; m++) {
                int row  = wm*32 + m*16 + (lane & 15);
                int coff = kh*2 + (lane >> 4);
                uint32_t so = SWZ64((uint32_t)(row*64 + coff*16));
                ldmx4(ah[m], stg + OFF_AH + so);
                ldmx4(al[m], stg + OFF_AL + so);
            }
            // --- B fragments (hi, lo): 8 n8 tiles, loaded as 4 x4-pairs ---
            uint32_t bh[8][2], bl[8][2];
#pragma unroll
            for (int p = 0; p < 4; p++) {
                int row  = wn*64 + p*16 + (lane & 7) + ((lane >> 4) & 1) * 8;
                int coff = kh*2 + ((lane >> 3) & 1);
                uint32_t so = SWZ64((uint32_t)(row*64 + coff*16));
                uint32_t t[4];
                ldmx4(t, stg + OFF_BH + so);
                bh[2*p][0]=t[0]; bh[2*p][1]=t[1]; bh[2*p+1][0]=t[2]; bh[2*p+1][1]=t[3];
                ldmx4(t, stg + OFF_BL + so);
                bl[2*p][0]=t[0]; bl[2*p][1]=t[1]; bl[2*p+1][0]=t[2]; bl[2*p+1][1]=t[3];
            }
            // --- 3 products x 16 independent MMAs ---
#pragma unroll
            for (int m = 0; m < 2; m++)
#pragma unroll
                for (int n = 0; n < 8; n++) mma16816(acc[m][n], ah[m], bh[n]);
#pragma unroll
            for (int m = 0; m < 2; m++)
#pragma unroll
                for (int n = 0; n < 8; n++) mma16816(acc[m][n], ah[m], bl[n]);
#pragma unroll
            for (int m = 0; m < 2; m++)
#pragma unroll
                for (int n = 0; n < 8; n++) mma16816(acc[m][n], al[m], bh[n]);
        }
        __syncthreads();
    }

    // ---- epilogue: accum -> g_cat ----
#pragma unroll
    for (int m = 0; m < 2; m++) {
        int rowA = r0 + wm*32 + m*16 + (lane >> 2);
#pragma unroll
        for (int n = 0; n < 8; n++) {
            int col = n0 + wn*64 + n*8 + (lane & 3)*2;
            float2 v0 = make_float2(acc[m][n][0], acc[m][n][1]);
            float2 v1 = make_float2(acc[m][n][2], acc[m][n][3]);
            *(float2*)(g_cat + (size_t)rowA*NCAT + col)     = v0;
            *(float2*)(g_cat + (size_t)(rowA+8)*NCAT + col) = v1;
        }
    }
}

// ================= K2e: z = (lin+bz)*silu(act+bza); colsums; zrows =================
__global__ void k2e_epi(const float* __restrict__ bz, const float* __restrict__ bza)
{
    int jc = blockIdx.x * 256 + threadIdx.x;      // 0..1023
    int rt = blockIdx.y;                          // 0..63 (64-row tiles)
    int h  = jc >> 7;
    float bzv = bz[jc], bzav = bza[jc];
    float s = 0.f;
    int rbase = rt * 64;
    int b = rbase >> 11;
#pragma unroll 4
    for (int i = 0; i < 64; i++) {
        int r = rbase + i;
        int l = r & (Ldim-1);
        float lin = g_cat[(size_t)r*NCAT + jc] + bzv;
        float a   = g_cat[(size_t)r*NCAT + DIMV + jc] + bzav;
        float zv  = lin * (a / (1.f + expf(-a)));
        if (l > h) s += zv;
        if (l < NH) g_zrows[b][l][jc] = zv;
    }
    g_spart[rt][jc] = s;
}

// ================= K1a: dt projection (warp per row) =================
__global__ void k1_dt(const float* __restrict__ x, const float* __restrict__ Wdt,
                      const float* __restrict__ bdt, const float* __restrict__ lna)
{
    int gw   = (blockIdx.x * blockDim.x + threadIdx.x) >> 5;
    int lane = threadIdx.x & 31;
    if (gw >= MROWS) return;
    const float* xr = x + (size_t)gw * DIMV;
    float acc[NH];
#pragma unroll
    for (int h = 0; h < NH; h++) acc[h] = 0.f;
    for (int k = lane; k < DIMV; k += 32) {
        float xv = xr[k];
#pragma unroll
        for (int h = 0; h < NH; h++) acc[h] += xv * Wdt[h*DIMV + k];
    }
#pragma unroll
    for (int h = 0; h < NH; h++)
        for (int off = 16; off; off >>= 1)
            acc[h] += __shfl_xor_sync(0xffffffffu, acc[h], off);
    if (lane == 0) {
        int b = gw >> 11, l = gw & (Ldim-1);
#pragma unroll
        for (int h = 0; h < NH; h++) {
            float v  = acc[h] + bdt[h];
            float sp = fmaxf(v, 0.f) + log1pf(expf(-fabsf(v)));
            g_lda[b][h][l] = -expf(lna[h]) * sp;
        }
    }
}

// ================= K1b: inclusive scan + exp =================
__global__ void k1b_scan()
{
    int b = blockIdx.x >> 3, h = blockIdx.x & 7;
    int t = threadIdx.x;
    const float* src = g_lda[b][h];
    int base = t * 8;
    float v[8]; float s = 0.f;
#pragma unroll
    for (int u = 0; u < 8; u++) { v[u] = src[base+u]; s += v[u]; }
    __shared__ float sm[256];
    sm[t] = s; __syncthreads();
    for (int d = 1; d < 256; d <<= 1) {
        float add = (t >= d) ? sm[t-d] : 0.f;
        __syncthreads();
        sm[t] += add;
        __syncthreads();
    }
    float run = sm[t] - s;
#pragma unroll
    for (int u = 0; u < 8; u++) { run += v[u]; g_Acum[b][h][base+u] = expf(run); }
}

// ================= K3: per-(b,h) stats =================
__device__ __forceinline__ float blockSum128(float v, float* sm)
{
    for (int off = 16; off; off >>= 1) v += __shfl_xor_sync(0xffffffffu, v, off);
    int w = threadIdx.x >> 5;
    if ((threadIdx.x & 31) == 0) sm[w] = v;
    __syncthreads();
    float r = sm[0] + sm[1] + sm[2] + sm[3];
    __syncthreads();
    return r;
}

__global__ void k3_stats(const float* __restrict__ hidden, const float* __restrict__ gnw,
                         float* __restrict__ out, int writeHidden)
{
    int b = blockIdx.x >> 3, h = blockIdx.x & 7;
    int i = threadIdx.x;
    int col = h*INNER + i;
    float S = 0.f;
#pragma unroll 8
    for (int t = 0; t < MROWS/64/Bdim; t++)
        S += g_spart[b*(MROWS/64/Bdim) + t][col];
    float c  = g_zrows[b][h][col];
    float tv = S + hidden[(b*NH+h)*INNER + i];

    __shared__ float sm[4];
    float mc = blockSum128(c,  sm) * (1.f/INNER);
    float mt = blockSum128(tv, sm) * (1.f/INNER);
    float dc = c - mc, dq = tv - mt;
    float vc = blockSum128(dc*dc, sm) * (1.f/INNER);
    float vt = blockSum128(dq*dq, sm) * (1.f/INNER);
    float cv = blockSum128(dc*dq, sm) * (1.f/INNER);
    if (i == 0) { g_vc[b][h]=vc; g_vt[b][h]=vt; g_cov[b][h]=cv; }
    float w = gnw[h];
    g_P[b][h][i] = dc * w;
    g_Q[b][h][i] = dq * w;
    if (writeHidden)
        out[(size_t)MROWS*DIMV + (b*NH+h)*INNER + i] = c + g_Acum[b][h][Ldim-1]*tv;
}

// ================= K4: rank-16 projections through W_y =================
__global__ void k4_proj(const float* __restrict__ Wy, const float* __restrict__ by,
                        const float* __restrict__ gnb)
{
    __shared__ float Ps[Bdim*NH*INNER];
    __shared__ float Qs[Bdim*NH*INNER];
    for (int idx = threadIdx.x; idx < Bdim*NH*INNER; idx += blockDim.x) {
        Ps[idx] = ((const float*)g_P)[idx];
        Qs[idx] = ((const float*)g_Q)[idx];
    }
    __syncthreads();
    int j    = (blockIdx.x * blockDim.x + threadIdx.x) >> 5;
    int lane = threadIdx.x & 31;
    if (j >= DIMV) return;
    const float* wrow = Wy + (size_t)j*DIMV;
    float gb = 0.f;
#pragma unroll
    for (int h = 0; h < NH; h++) {
        float aP0=0.f, aQ0=0.f, aP1=0.f, aQ1=0.f, aW=0.f;
#pragma unroll
        for (int kk = 0; kk < 4; kk++) {
            int ii = kk*32 + lane;
            float w = wrow[h*INNER + ii];
            aW  += w;
            aP0 += w * Ps[(0*NH+h)*INNER + ii];
            aQ0 += w * Qs[(0*NH+h)*INNER + ii];
            aP1 += w * Ps[(1*NH+h)*INNER + ii];
            aQ1 += w * Qs[(1*NH+h)*INNER + ii];
        }
        for (int off = 16; off; off >>= 1) {
            aP0 += __shfl_xor_sync(0xffffffffu, aP0, off);
            aQ0 += __shfl_xor_sync(0xffffffffu, aQ0, off);
            aP1 += __shfl_xor_sync(0xffffffffu, aP1, off);
            aQ1 += __shfl_xor_sync(0xffffffffu, aQ1, off);
            aW  += __shfl_xor_sync(0xffffffffu, aW,  off);
        }
        if (lane == 0) {
            g_PW[0][h][j] = aP0;  g_QW[0][h][j] = aQ0;
            g_PW[1][h][j] = aP1;  g_QW[1][h][j] = aQ1;
            gb += gnb[h] * aW;
        }
    }
    if (lane == 0) g_GW[j] = by[j] + gb;
}

// ================= K5: final combine =================
__global__ void k5_final(float* __restrict__ out, const float* __restrict__ bya)
{
    int r = blockIdx.x;
    int b = r >> 11, l = r & (Ldim-1);
    __shared__ float cP[NH], cQ[NH];
    if (threadIdx.x < NH) {
        int h = threadIdx.x;
        float A   = g_Acum[b][h][l];
        float var = g_vc[b][h] + 2.f*A*g_cov[b][h] + A*A*g_vt[b][h];
        float inv = rsqrtf(var + EPSV);
        cP[h] = inv;
        cQ[h] = A * inv;
    }
    __syncthreads();
    for (int j = threadIdx.x; j < DIMV; j += blockDim.x) {
        float y0 = g_GW[j];
#pragma unroll
        for (int h = 0; h < NH; h++)
            y0 += cP[h]*g_PW[b][h][j] + cQ[h]*g_QW[b][h][j];
        float ya = g_cat[(size_t)r*NCAT + 2*DIMV + j] + bya[j];
        out[(size_t)r*DIMV + j] = y0 * (ya / (1.f + expf(-ya)));
    }
}

// ================= launch =================
extern "C" void kernel_launch(void* const* d_in, const int* in_sizes, int n_in,
                              void* d_out, int out_size)
{
    const float* x    = (const float*)d_in[0];
    const float* hid  = (const float*)d_in[1];
    const float* W_z  = (const float*)d_in[2];
    const float* b_z  = (const float*)d_in[3];
    const float* W_za = (const float*)d_in[4];
    const float* b_za = (const float*)d_in[5];
    const float* W_y  = (const float*)d_in[6];
    const float* b_y  = (const float*)d_in[7];
    const float* W_ya = (const float*)d_in[8];
    const float* b_ya = (const float*)d_in[9];
    const float* W_dt = (const float*)d_in[10];
    const float* b_dt = (const float*)d_in[11];
    const float* ln_a = (const float*)d_in[12];
    const float* gn_w = (const float*)d_in[13];
    const float* gn_b = (const float*)d_in[14];
    float* out = (float*)d_out;
    int writeHidden = (out_size >= MROWS*DIMV + Bdim*NH*INNER) ? 1 : 0;

    cudaFuncSetAttribute(kgemm_mma, cudaFuncAttributeMaxDynamicSharedMemorySize, GEMM_SMEM);

    __nv_bfloat16 *xh, *xl, *wh, *wl;
    cudaGetSymbolAddress((void**)&xh, g_xh);
    cudaGetSymbolAddress((void**)&xl, g_xl);
    cudaGetSymbolAddress((void**)&wh, g_wh);
    cudaGetSymbolAddress((void**)&wl, g_wl);

    // hi/lo conversions
    kconv<<<(MROWS*DIMV/4 + 255)/256, 256>>>(x, xh, xl, MROWS*DIMV/4);
    kconv<<<(DIMV*DIMV/4 + 255)/256, 256>>>(W_z,  wh,               wl,               DIMV*DIMV/4);
    kconv<<<(DIMV*DIMV/4 + 255)/256, 256>>>(W_za, wh + DIMV*DIMV,   wl + DIMV*DIMV,   DIMV*DIMV/4);
    kconv<<<(DIMV*DIMV/4 + 255)/256, 256>>>(W_ya, wh + 2*DIMV*DIMV, wl + 2*DIMV*DIMV, DIMV*DIMV/4);

    k1_dt  <<<MROWS/8, 256>>>(x, W_dt, b_dt, ln_a);
    k1b_scan<<<Bdim*NH, 256>>>();

    dim3 gg(NCAT/128, MROWS/128);
    kgemm_mma<<<gg, 256, GEMM_SMEM>>>();

    dim3 ge(DIMV/256, MROWS/64);
    k2e_epi<<<ge, 256>>>(b_z, b_za);

    k3_stats<<<Bdim*NH, INNER>>>(hid, gn_w, out, writeHidden);
    k4_proj<<<DIMV/8, 256>>>(W_y, b_y, gn_b);
    k5_final<<<MROWS, 256>>>(out, b_ya);
}